// round 12
// baseline (speedup 1.0000x reference)
#include <cuda_runtime.h>

// Fixed problem shapes
#define B_ 16
#define T_ 8
#define C_ 2048
#define H_ 16
#define D_ 128
#define MAXSEQ 4096
#define STARTPOS 4088
#define S_ 4096
#define QKV_STRIDE (3*C_)
#define M_ (B_*T_)          // 128
#define CH_ 512             // attention s-chunk
#define NCH 8               // S_/CH_
#define QKV_KS 6
#define PROJ_KS 18

// Scratch (static device globals: allocation-free)
__device__ float g_xT  [C_*M_];                     // x transposed [2048][128]
__device__ float g_qkv [M_*3*C_];                   // [128][6144]
__device__ float g_qkvp[(QKV_KS-1)*M_*3*C_];        // split-K partials
__device__ float g_attT[C_*M_];                     // attention out transposed
__device__ float g_outp[(PROJ_KS-1)*M_*C_];         // proj split-K partials
__device__ float g_py  [(size_t)B_*H_*NCH*T_*D_];   // PV partials
__device__ float g_pm  [B_*H_*NCH*T_];              // chunk maxes
__device__ float g_pl  [B_*H_*NCH*T_];              // chunk sums

typedef unsigned long long u64;

__device__ __forceinline__ u64 dupf(float x) {
    u64 r; unsigned xi = __float_as_uint(x);
    asm("mov.b64 %0, {%1, %1};" : "=l"(r) : "r"(xi));
    return r;
}
__device__ __forceinline__ void fma2(u64& d, u64 a, u64 b) {
    asm("fma.rn.f32x2 %0, %1, %2, %0;" : "+l"(d) : "l"(a), "l"(b));
}
__device__ __forceinline__ float2 unpk(u64 v) {
    unsigned lo, hi;
    asm("mov.b64 {%0, %1}, %2;" : "=r"(lo), "=r"(hi) : "l"(v));
    return make_float2(__uint_as_float(lo), __uint_as_float(hi));
}
__device__ __forceinline__ float hsum2(u64 v) { float2 f = unpk(v); return f.x + f.y; }

__device__ __forceinline__ void cp16(unsigned dst, const void* src) {
    asm volatile("cp.async.cg.shared.global [%0], [%1], 16;\n" :: "r"(dst), "l"(src));
}
#define CP_COMMIT()  asm volatile("cp.async.commit_group;\n" ::: "memory")
#define CP_WAIT(n)   asm volatile("cp.async.wait_group %0;\n" :: "n"(n) : "memory")

// ---------------------------------------------------------------------------
// transpose x[128][2048] -> xT[2048][128]
// ---------------------------------------------------------------------------
__global__ __launch_bounds__(256) void transpose_kernel(const float* __restrict__ x,
                                                        float* __restrict__ xT) {
    int idx = blockIdx.x * 256 + threadIdx.x;
    int r = idx >> 11;
    int c = idx & 2047;
    xT[c * M_ + r] = x[idx];
}

// ---------------------------------------------------------------------------
// GEMM: C[128][N] = AT^T[128][2048] @ B[2048][N] + bias, split-K (KS slices).
// ---------------------------------------------------------------------------
__global__ __launch_bounds__(256) void gemm_splitk_kernel(
    const float* __restrict__ AT, const float* __restrict__ Bw,
    const float* __restrict__ bias, float* __restrict__ Cc,
    float* __restrict__ Pp, int N, int KS)
{
    __shared__ float As[2][8][128];
    __shared__ float Bs[2][8][128];

    const int tid = threadIdx.x;
    const int tx = tid & 15;
    const int ty = tid >> 4;
    const int n0 = blockIdx.x * 128;
    const int slice = blockIdx.y;

    const int KBTOT = 256;
    const int kb0 = (slice * KBTOT) / KS;
    const int kb1 = ((slice + 1) * KBTOT) / KS;

    const int lr = tid >> 5;
    const int lc = tid & 31;
    unsigned sA = (unsigned)__cvta_generic_to_shared(&As[0][0][0]);
    unsigned sB = (unsigned)__cvta_generic_to_shared(&Bs[0][0][0]);

    u64 acc[4][8];
    #pragma unroll
    for (int p = 0; p < 4; p++)
        #pragma unroll
        for (int n = 0; n < 8; n++) acc[p][n] = 0ull;

    {
        int k = kb0 * 8 + lr;
        cp16(sA + (unsigned)(lr * 128 + lc * 4) * 4u, AT + (size_t)k * M_ + lc * 4);
        cp16(sB + (unsigned)(lr * 128 + lc * 4) * 4u, Bw + (size_t)k * N + n0 + lc * 4);
        CP_COMMIT();
    }

    for (int kb = kb0; kb < kb1; kb++) {
        int buf = (kb - kb0) & 1;
        if (kb + 1 < kb1) {
            int nb = buf ^ 1;
            int k = (kb + 1) * 8 + lr;
            cp16(sA + (unsigned)(nb * 1024 + lr * 128 + lc * 4) * 4u, AT + (size_t)k * M_ + lc * 4);
            cp16(sB + (unsigned)(nb * 1024 + lr * 128 + lc * 4) * 4u, Bw + (size_t)k * N + n0 + lc * 4);
            CP_COMMIT();
            CP_WAIT(1);
        } else {
            CP_WAIT(0);
        }
        __syncthreads();

        #pragma unroll
        for (int kk = 0; kk < 8; kk++) {
            ulonglong2 a0 = *(const ulonglong2*)&As[buf][kk][ty * 4];
            ulonglong2 a1 = *(const ulonglong2*)&As[buf][kk][64 + ty * 4];
            float4 b0 = *(const float4*)&Bs[buf][kk][tx * 4];
            float4 b1 = *(const float4*)&Bs[buf][kk][64 + tx * 4];
            u64 bd[8];
            bd[0] = dupf(b0.x); bd[1] = dupf(b0.y); bd[2] = dupf(b0.z); bd[3] = dupf(b0.w);
            bd[4] = dupf(b1.x); bd[5] = dupf(b1.y); bd[6] = dupf(b1.z); bd[7] = dupf(b1.w);
            #pragma unroll
            for (int n = 0; n < 8; n++) {
                fma2(acc[0][n], a0.x, bd[n]);
                fma2(acc[1][n], a0.y, bd[n]);
                fma2(acc[2][n], a1.x, bd[n]);
                fma2(acc[3][n], a1.y, bd[n]);
            }
        }
        __syncthreads();
    }

    float* dst = (slice == 0) ? Cc : Pp + (size_t)(slice - 1) * M_ * N;
    float4 bi0 = make_float4(0.f, 0.f, 0.f, 0.f), bi1 = bi0;
    if (slice == 0) {
        bi0 = *(const float4*)(bias + n0 + tx * 4);
        bi1 = *(const float4*)(bias + n0 + 64 + tx * 4);
    }
    #pragma unroll
    for (int p = 0; p < 4; p++) {
        int mr = (p < 2) ? (ty * 4 + 2 * p) : (64 + ty * 4 + 2 * (p - 2));
        float2 u0 = unpk(acc[p][0]), u1 = unpk(acc[p][1]), u2 = unpk(acc[p][2]), u3 = unpk(acc[p][3]);
        float2 u4 = unpk(acc[p][4]), u5 = unpk(acc[p][5]), u6 = unpk(acc[p][6]), u7 = unpk(acc[p][7]);
        float4 lo0 = make_float4(u0.x + bi0.x, u1.x + bi0.y, u2.x + bi0.z, u3.x + bi0.w);
        float4 hi0 = make_float4(u0.y + bi0.x, u1.y + bi0.y, u2.y + bi0.z, u3.y + bi0.w);
        float4 lo1 = make_float4(u4.x + bi1.x, u5.x + bi1.y, u6.x + bi1.z, u7.x + bi1.w);
        float4 hi1 = make_float4(u4.y + bi1.x, u5.y + bi1.y, u6.y + bi1.z, u7.y + bi1.w);
        *(float4*)(dst + (size_t)mr * N + n0 + tx * 4)            = lo0;
        *(float4*)(dst + (size_t)(mr + 1) * N + n0 + tx * 4)      = hi0;
        *(float4*)(dst + (size_t)mr * N + n0 + 64 + tx * 4)       = lo1;
        *(float4*)(dst + (size_t)(mr + 1) * N + n0 + 64 + tx * 4) = hi1;
    }
}

// dst[i] += sum_p parts[p][i]
__global__ __launch_bounds__(256) void addparts_kernel(float* __restrict__ dst,
                                                       const float* __restrict__ parts,
                                                       int nparts, int n4) {
    int i = blockIdx.x * 256 + threadIdx.x;
    if (i >= n4) return;
    float4 v = ((float4*)dst)[i];
    for (int p = 0; p < nparts; p++) {
        float4 a = ((const float4*)parts)[(size_t)p * n4 + i];
        v.x += a.x; v.y += a.y; v.z += a.z; v.w += a.w;
    }
    ((float4*)dst)[i] = v;
}

// ---------------------------------------------------------------------------
// Attention chunk kernel: block per (b,h,chunk), 256 threads, 2048 blocks.
// 32-row K tiles x2 buffers; 4-row q amortization; 1 sync/tile via pp x2;
// chunk-max folded into combine.
// ---------------------------------------------------------------------------
// smem float offsets
#define A_TILE_OFF 0                  // 2 x 32x128 = 8192
#define A_QS_OFF   8192               // 8 x 132 = 1056 (padded stride)
#define A_SC_OFF   9248               // 512*8 = 4096
#define A_PP_OFF   13344              // 2 x 256*10 = 5120
#define A_RED_OFF  18464              // wred 64 + smj 8 + slj 8
#define A_SMEM_FLOATS 18544
#define A_SMEM_BYTES  (A_SMEM_FLOATS*4)
#define QPAD 132

__device__ __forceinline__ int swiz(int r, int c) {   // 16B-chunk swizzle, 512B row
    return (c & 24) | ((c & 7) ^ (r & 7));
}

__global__ __launch_bounds__(256, 3) void attn_chunk_kernel(
    const float* __restrict__ k_cache,
    const float* __restrict__ v_cache,
    const float* __restrict__ qkv)
{
    extern __shared__ float sm[];
    const int tid  = threadIdx.x;
    const int bx   = blockIdx.x;
    const int ch   = bx & 7;
    const int bh   = bx >> 3;
    const int b    = bh >> 4;
    const int h    = bh & 15;
    const int w    = tid >> 5;
    const int lane = tid & 31;
    const int s_chunk0 = ch * CH_;

    float* tile = sm + A_TILE_OFF;
    float* qs   = sm + A_QS_OFF;
    float* sc   = sm + A_SC_OFF;
    float* pp   = sm + A_PP_OFF;          // 2 buffers of 2560
    float* wred = sm + A_RED_OFF;         // [8 warps][8]
    float* smj  = sm + A_RED_OFF + 64;    // chunk max [8]
    float* slj  = sm + A_RED_OFF + 72;    // chunk sum [8]

    unsigned tile_s = (unsigned)__cvta_generic_to_shared(tile);

    // tile loader: 1024 16B chunks per tile, thread does 4
    auto load_tile = [&](int tt, int buf) {
        int s0 = s_chunk0 + tt * 32;
        #pragma unroll
        for (int i = 0; i < 4; i++) {
            int m = tid + 256 * i;
            int rr2 = m >> 5, cc = m & 31;
            int s = s0 + rr2;
            const float* src = (s >= STARTPOS)
                ? qkv + (size_t)(b * T_ + (s - STARTPOS)) * QKV_STRIDE + C_ + h * D_ + cc * 4
                : k_cache + ((size_t)(b * H_ + h) * MAXSEQ + s) * (size_t)D_ + cc * 4;
            unsigned dst = tile_s + ((unsigned)buf * 1024u + (unsigned)(rr2 * 32 + swiz(rr2, cc))) * 16u;
            cp16(dst, src);
        }
        CP_COMMIT();
    };

    // prologue: issue tile 0 load, then stage q (scaled, padded stride QPAD)
    load_tile(0, 0);
    const float scale = 0.08838834764831845f;
    for (int f = tid; f < T_ * D_; f += 256) {
        int j = f >> 7, d = f & 127;
        qs[j * QPAD + d] = qkv[(size_t)(b * T_ + j) * QKV_STRIDE + h * D_ + d] * scale;
    }

    // ------- score loop: 16 tiles, 1 sync per tile --------------------------
    const int e  = w;                     // warp owns d-chunks e*4..e*4+3
    const int rr = lane & 7;              // row base
    const int jq = lane >> 3;             // 0..3 j-quarter (2 j's)
    unsigned kbase[4];
    #pragma unroll
    for (int i = 0; i < 4; i++) {
        int c = e * 4 + i;
        kbase[i] = (unsigned)(rr * 512 + ((c & 24) | ((c & 7) ^ rr)) * 16);
    }
    const float* qA = qs + (jq * 2) * QPAD;
    const float* qB = qA + QPAD;
    const int r_c = tid >> 3, j_c = tid & 7;   // combine mapping
    float cmax = -3.4e38f;

    #pragma unroll 1
    for (int tt = 0; tt <= 16; tt++) {
        CP_WAIT(0);
        __syncthreads();
        if (tt + 1 < 16) load_tile(tt + 1, (tt + 1) & 1);

        if (tt > 0) {              // combine tile tt-1 from pp[(tt-1)&1]
            const float* ppb = pp + ((tt - 1) & 1) * 2560;
            float v = 0.f;
            #pragma unroll
            for (int ee = 0; ee < 8; ee++) v += ppb[(ee * 32 + r_c) * 10 + j_c];
            cmax = fmaxf(cmax, v);
            sc[((tt - 1) * 32 + r_c) * 8 + j_c] = v;
        }

        if (tt < 16) {             // compute tile tt into pp[tt&1]
            const char* tb = (const char*)tile + (tt & 1) * 16384;
            u64 acc[4][2];
            #pragma unroll
            for (int g = 0; g < 4; g++) { acc[g][0] = 0ull; acc[g][1] = 0ull; }
            #pragma unroll
            for (int i = 0; i < 4; i++) {
                int c = e * 4 + i;
                ulonglong2 qa = *(const ulonglong2*)(qA + c * 4);
                ulonglong2 qb = *(const ulonglong2*)(qB + c * 4);
                #pragma unroll
                for (int g = 0; g < 4; g++) {
                    ulonglong2 kk = *(const ulonglong2*)(tb + kbase[i] + g * 4096);
                    fma2(acc[g][0], kk.x, qa.x); fma2(acc[g][0], kk.y, qa.y);
                    fma2(acc[g][1], kk.x, qb.x); fma2(acc[g][1], kk.y, qb.y);
                }
            }
            float* ppb = pp + (tt & 1) * 2560;
            #pragma unroll
            for (int g = 0; g < 4; g++) {
                int row = rr + 8 * g;
                *(float2*)(ppb + (e * 32 + row) * 10 + jq * 2) =
                    make_float2(hsum2(acc[g][0]), hsum2(acc[g][1]));
            }
        }
    }

    // ------- chunk max from per-thread cmax (r_c fixed per thread) ----------
    pp[tid] = cmax;               // pp[0] buffer free now; [r_c*8 + j_c] == tid
    __syncthreads();
    if (tid < 8) {
        float m = pp[tid];
        for (int r2 = 1; r2 < 32; r2++) m = fmaxf(m, pp[r2 * 8 + tid]);
        smj[tid] = m;
    }
    __syncthreads();

    // ------- exp in place + row sums ----------------------------------------
    {
        float m[8], sum[8];
        #pragma unroll
        for (int j = 0; j < 8; j++) { m[j] = smj[j]; sum[j] = 0.f; }
        for (int s = tid; s < CH_; s += 256) {
            float4 a = *(const float4*)(sc + s * 8);
            float4 c = *(const float4*)(sc + s * 8 + 4);
            a.x = __expf(a.x - m[0]); a.y = __expf(a.y - m[1]);
            a.z = __expf(a.z - m[2]); a.w = __expf(a.w - m[3]);
            c.x = __expf(c.x - m[4]); c.y = __expf(c.y - m[5]);
            c.z = __expf(c.z - m[6]); c.w = __expf(c.w - m[7]);
            *(float4*)(sc + s * 8)     = a;
            *(float4*)(sc + s * 8 + 4) = c;
            sum[0] += a.x; sum[1] += a.y; sum[2] += a.z; sum[3] += a.w;
            sum[4] += c.x; sum[5] += c.y; sum[6] += c.z; sum[7] += c.w;
        }
        #pragma unroll
        for (int o = 16; o; o >>= 1)
            #pragma unroll
            for (int j = 0; j < 8; j++) sum[j] += __shfl_xor_sync(~0u, sum[j], o);
        if (lane == 0)
            #pragma unroll
            for (int j = 0; j < 8; j++) wred[w * 8 + j] = sum[j];
    }
    __syncthreads();
    if (tid < 8) {
        float s = 0.f;
        for (int ww = 0; ww < 8; ww++) s += wred[ww * 8 + tid];
        slj[tid] = s;
    }

    // ------- PV: warp w covers 64 rows, lanes across d ----------------------
    u64 acc[8][2];
    #pragma unroll
    for (int j = 0; j < 8; j++) { acc[j][0] = 0ull; acc[j][1] = 0ull; }
    const int db = lane * 4;
    const int lbeg = w * 64;
    for (int sl = lbeg; sl < lbeg + 64; sl += 4) {
        #pragma unroll
        for (int u = 0; u < 4; u++) {
            int local = sl + u;
            int ss = s_chunk0 + local;
            const float* vrow = (ss >= STARTPOS)
                ? qkv + (size_t)(b * T_ + (ss - STARTPOS)) * QKV_STRIDE + 2 * C_ + h * D_
                : v_cache + ((size_t)(b * H_ + h) * MAXSEQ + ss) * (size_t)D_;
            ulonglong2 vv = *(const ulonglong2*)(vrow + db);
            float4 p0 = *(const float4*)(sc + local * 8);
            float4 p1 = *(const float4*)(sc + local * 8 + 4);
            float pj[8] = {p0.x, p0.y, p0.z, p0.w, p1.x, p1.y, p1.z, p1.w};
            #pragma unroll
            for (int j = 0; j < 8; j++) {
                u64 pd = dupf(pj[j]);
                fma2(acc[j][0], vv.x, pd);
                fma2(acc[j][1], vv.y, pd);
            }
        }
    }
    __syncthreads();
    float* ypart = tile;   // reuse: [8 warps][1024] = 8192 floats
    #pragma unroll
    for (int j = 0; j < 8; j++) {
        ulonglong2 st; st.x = acc[j][0]; st.y = acc[j][1];
        *(ulonglong2*)&ypart[w * 1024 + j * 128 + db] = st;
    }
    __syncthreads();
    for (int f = tid; f < 1024; f += 256) {
        float sum = 0.f;
        #pragma unroll
        for (int ww = 0; ww < 8; ww++) sum += ypart[ww * 1024 + f];
        g_py[(size_t)bx * 1024 + f] = sum;
    }
    if (tid < 8) {
        g_pm[bx * 8 + tid] = smj[tid];
        g_pl[bx * 8 + tid] = slj[tid];
    }
}

// ---------------------------------------------------------------------------
// Combine chunk partials per (b,h): log-sum-exp merge, write attT.
// ---------------------------------------------------------------------------
__global__ __launch_bounds__(256) void attn_reduce_kernel(float* __restrict__ attT)
{
    __shared__ float wgt[NCH][8];
    __shared__ float Lj[8];
    const int bh  = blockIdx.x;
    const int b   = bh >> 4;
    const int h   = bh & 15;
    const int tid = threadIdx.x;

    if (tid < 8) {
        int j = tid;
        float M = -3.4e38f;
        #pragma unroll
        for (int c = 0; c < NCH; c++)
            M = fmaxf(M, g_pm[(bh * NCH + c) * 8 + j]);
        float L = 0.f;
        #pragma unroll
        for (int c = 0; c < NCH; c++) {
            float wq = __expf(g_pm[(bh * NCH + c) * 8 + j] - M);
            wgt[c][j] = wq;
            L += g_pl[(bh * NCH + c) * 8 + j] * wq;
        }
        Lj[j] = L;
    }
    __syncthreads();

    for (int f = tid; f < 1024; f += 256) {
        int j = f >> 7, d = f & 127;
        float sum = 0.f;
        #pragma unroll
        for (int c = 0; c < NCH; c++)
            sum += g_py[(size_t)(bh * NCH + c) * 1024 + f] * wgt[c][j];
        attT[(size_t)(h * D_ + d) * M_ + b * T_ + j] = sum / Lj[j];
    }
}

// ---------------------------------------------------------------------------
extern "C" void kernel_launch(void* const* d_in, const int* in_sizes, int n_in,
                              void* d_out, int out_size)
{
    const float* x  = (const float*)d_in[0];
    const float* kc = (const float*)d_in[1];
    const float* vc = (const float*)d_in[2];
    const float* wa = (const float*)d_in[3];
    const float* ba = (const float*)d_in[4];
    const float* wp = (const float*)d_in[5];
    const float* bp = (const float*)d_in[6];
    float* out = (float*)d_out;

    float *xT, *qkv, *qkvp, *attT, *outp;
    cudaGetSymbolAddress((void**)&xT,   g_xT);
    cudaGetSymbolAddress((void**)&qkv,  g_qkv);
    cudaGetSymbolAddress((void**)&qkvp, g_qkvp);
    cudaGetSymbolAddress((void**)&attT, g_attT);
    cudaGetSymbolAddress((void**)&outp, g_outp);

    cudaFuncSetAttribute(attn_chunk_kernel,
                         cudaFuncAttributeMaxDynamicSharedMemorySize, A_SMEM_BYTES);

    // 1) transpose x -> xT
    transpose_kernel<<<(M_*C_)/256, 256>>>(x, xT);
    // 2) QKV GEMM, split-K 6 (48x6 = 288 blocks)
    gemm_splitk_kernel<<<dim3(3*C_/128, QKV_KS), 256>>>(xT, wa, ba, qkv, qkvp, 3*C_, QKV_KS);
    // 3) reduce partials into qkv
    addparts_kernel<<<(M_*3*C_/4 + 255)/256, 256>>>(qkv, qkvp, QKV_KS-1, M_*3*C_/4);
    // 4) attention chunks (2048 blocks) + merge
    attn_chunk_kernel<<<B_*H_*NCH, 256, A_SMEM_BYTES>>>(kc, vc, qkv);
    attn_reduce_kernel<<<B_*H_, 256>>>(attT);
    // 5) proj GEMM, split-K 18 (16x18 = 288 blocks)
    gemm_splitk_kernel<<<dim3(C_/128, PROJ_KS), 256>>>(attT, wp, bp, out, outp, C_, PROJ_KS);
    // 6) reduce partials into out
    addparts_kernel<<<(M_*C_/4 + 255)/256, 256>>>(out, outp, PROJ_KS-1, M_*C_/4);
}

// round 13
// speedup vs baseline: 1.0274x; 1.0274x over previous
#include <cuda_runtime.h>

// Fixed problem shapes
#define B_ 16
#define T_ 8
#define C_ 2048
#define H_ 16
#define D_ 128
#define MAXSEQ 4096
#define STARTPOS 4088
#define S_ 4096
#define QKV_STRIDE (3*C_)
#define M_ (B_*T_)          // 128
#define CH_ 512             // attention s-chunk
#define NCH 8               // S_/CH_
#define QKV_KS 6
#define PROJ_KS 18

// Scratch (static device globals: allocation-free)
__device__ float g_xT  [C_*M_];                     // x transposed [2048][128]
__device__ float g_qkv [M_*3*C_];                   // [128][6144]
__device__ float g_qkvp[(QKV_KS-1)*M_*3*C_];        // split-K partials
__device__ float g_attT[C_*M_];                     // attention out transposed
__device__ float g_outp[(PROJ_KS-1)*M_*C_];         // proj split-K partials
__device__ float g_py  [(size_t)B_*H_*NCH*T_*D_];   // PV partials
__device__ float g_pm  [B_*H_*NCH*T_];              // chunk maxes
__device__ float g_pl  [B_*H_*NCH*T_];              // chunk sums

typedef unsigned long long u64;

__device__ __forceinline__ u64 dupf(float x) {
    u64 r; unsigned xi = __float_as_uint(x);
    asm("mov.b64 %0, {%1, %1};" : "=l"(r) : "r"(xi));
    return r;
}
__device__ __forceinline__ void fma2(u64& d, u64 a, u64 b) {
    asm("fma.rn.f32x2 %0, %1, %2, %0;" : "+l"(d) : "l"(a), "l"(b));
}
__device__ __forceinline__ float2 unpk(u64 v) {
    unsigned lo, hi;
    asm("mov.b64 {%0, %1}, %2;" : "=r"(lo), "=r"(hi) : "l"(v));
    return make_float2(__uint_as_float(lo), __uint_as_float(hi));
}
__device__ __forceinline__ float hsum2(u64 v) { float2 f = unpk(v); return f.x + f.y; }

__device__ __forceinline__ void cp16(unsigned dst, const void* src) {
    asm volatile("cp.async.cg.shared.global [%0], [%1], 16;\n" :: "r"(dst), "l"(src));
}
#define CP_COMMIT()  asm volatile("cp.async.commit_group;\n" ::: "memory")
#define CP_WAIT(n)   asm volatile("cp.async.wait_group %0;\n" :: "n"(n) : "memory")

// ---------------------------------------------------------------------------
// transpose x[128][2048] -> xT[2048][128]
// ---------------------------------------------------------------------------
__global__ __launch_bounds__(256) void transpose_kernel(const float* __restrict__ x,
                                                        float* __restrict__ xT) {
    int idx = blockIdx.x * 256 + threadIdx.x;
    int r = idx >> 11;
    int c = idx & 2047;
    xT[c * M_ + r] = x[idx];
}

// ---------------------------------------------------------------------------
// GEMM: C[128][N] = AT^T[128][2048] @ B[2048][N] + bias, split-K (KS slices).
// 4-stage cp.async pipeline (3 x 8KB tiles in flight per CTA).
// ---------------------------------------------------------------------------
__global__ __launch_bounds__(256) void gemm_splitk_kernel(
    const float* __restrict__ AT, const float* __restrict__ Bw,
    const float* __restrict__ bias, float* __restrict__ Cc,
    float* __restrict__ Pp, int N, int KS)
{
    __shared__ float As[4][8][128];
    __shared__ float Bs[4][8][128];

    const int tid = threadIdx.x;
    const int tx = tid & 15;
    const int ty = tid >> 4;
    const int n0 = blockIdx.x * 128;
    const int slice = blockIdx.y;

    const int KBTOT = 256;
    const int kb0 = (slice * KBTOT) / KS;
    const int kb1 = ((slice + 1) * KBTOT) / KS;

    const int lr = tid >> 5;
    const int lc = tid & 31;
    unsigned sA = (unsigned)__cvta_generic_to_shared(&As[0][0][0]);
    unsigned sB = (unsigned)__cvta_generic_to_shared(&Bs[0][0][0]);

    u64 acc[4][8];
    #pragma unroll
    for (int p = 0; p < 4; p++)
        #pragma unroll
        for (int n = 0; n < 8; n++) acc[p][n] = 0ull;

    auto issue = [&](int kb, int buf) {
        int k = kb * 8 + lr;
        cp16(sA + (unsigned)(buf * 1024 + lr * 128 + lc * 4) * 4u, AT + (size_t)k * M_ + lc * 4);
        cp16(sB + (unsigned)(buf * 1024 + lr * 128 + lc * 4) * 4u, Bw + (size_t)k * N + n0 + lc * 4);
        CP_COMMIT();
    };

    // prologue: 3 tiles in flight
    issue(kb0, 0);
    if (kb0 + 1 < kb1) issue(kb0 + 1, 1);
    if (kb0 + 2 < kb1) issue(kb0 + 2, 2);

    for (int kb = kb0; kb < kb1; kb++) {
        int rem = kb1 - 1 - kb;
        if (rem >= 2)      { CP_WAIT(2); }
        else if (rem == 1) { CP_WAIT(1); }
        else               { CP_WAIT(0); }
        __syncthreads();
        if (kb + 3 < kb1) issue(kb + 3, (kb + 3 - kb0) & 3);

        int buf = (kb - kb0) & 3;
        #pragma unroll
        for (int kk = 0; kk < 8; kk++) {
            ulonglong2 a0 = *(const ulonglong2*)&As[buf][kk][ty * 4];
            ulonglong2 a1 = *(const ulonglong2*)&As[buf][kk][64 + ty * 4];
            float4 b0 = *(const float4*)&Bs[buf][kk][tx * 4];
            float4 b1 = *(const float4*)&Bs[buf][kk][64 + tx * 4];
            u64 bd[8];
            bd[0] = dupf(b0.x); bd[1] = dupf(b0.y); bd[2] = dupf(b0.z); bd[3] = dupf(b0.w);
            bd[4] = dupf(b1.x); bd[5] = dupf(b1.y); bd[6] = dupf(b1.z); bd[7] = dupf(b1.w);
            #pragma unroll
            for (int n = 0; n < 8; n++) {
                fma2(acc[0][n], a0.x, bd[n]);
                fma2(acc[1][n], a0.y, bd[n]);
                fma2(acc[2][n], a1.x, bd[n]);
                fma2(acc[3][n], a1.y, bd[n]);
            }
        }
    }

    float* dst = (slice == 0) ? Cc : Pp + (size_t)(slice - 1) * M_ * N;
    float4 bi0 = make_float4(0.f, 0.f, 0.f, 0.f), bi1 = bi0;
    if (slice == 0) {
        bi0 = *(const float4*)(bias + n0 + tx * 4);
        bi1 = *(const float4*)(bias + n0 + 64 + tx * 4);
    }
    #pragma unroll
    for (int p = 0; p < 4; p++) {
        int mr = (p < 2) ? (ty * 4 + 2 * p) : (64 + ty * 4 + 2 * (p - 2));
        float2 u0 = unpk(acc[p][0]), u1 = unpk(acc[p][1]), u2 = unpk(acc[p][2]), u3 = unpk(acc[p][3]);
        float2 u4 = unpk(acc[p][4]), u5 = unpk(acc[p][5]), u6 = unpk(acc[p][6]), u7 = unpk(acc[p][7]);
        float4 lo0 = make_float4(u0.x + bi0.x, u1.x + bi0.y, u2.x + bi0.z, u3.x + bi0.w);
        float4 hi0 = make_float4(u0.y + bi0.x, u1.y + bi0.y, u2.y + bi0.z, u3.y + bi0.w);
        float4 lo1 = make_float4(u4.x + bi1.x, u5.x + bi1.y, u6.x + bi1.z, u7.x + bi1.w);
        float4 hi1 = make_float4(u4.y + bi1.x, u5.y + bi1.y, u6.y + bi1.z, u7.y + bi1.w);
        *(float4*)(dst + (size_t)mr * N + n0 + tx * 4)            = lo0;
        *(float4*)(dst + (size_t)(mr + 1) * N + n0 + tx * 4)      = hi0;
        *(float4*)(dst + (size_t)mr * N + n0 + 64 + tx * 4)       = lo1;
        *(float4*)(dst + (size_t)(mr + 1) * N + n0 + 64 + tx * 4) = hi1;
    }
}

// dst[i] += sum_p parts[p][i]
__global__ __launch_bounds__(256) void addparts_kernel(float* __restrict__ dst,
                                                       const float* __restrict__ parts,
                                                       int nparts, int n4) {
    int i = blockIdx.x * 256 + threadIdx.x;
    if (i >= n4) return;
    float4 v = ((float4*)dst)[i];
    for (int p = 0; p < nparts; p++) {
        float4 a = ((const float4*)parts)[(size_t)p * n4 + i];
        v.x += a.x; v.y += a.y; v.z += a.z; v.w += a.w;
    }
    ((float4*)dst)[i] = v;
}

// ---------------------------------------------------------------------------
// Attention chunk kernel (R11 proven version, reverted verbatim):
// block per (b,h,chunk), 256 threads, 2048 blocks, 32-row K tiles x2 buffers.
// Score mapping: warp = e (4 d-chunks), lane = (rr 0..15, jh 0..1).
// ---------------------------------------------------------------------------
// smem float offsets
#define A_TILE_OFF 0                  // 2 x 32x128 = 8192
#define A_QS_OFF   8192               // 8 x 132 = 1056 (padded stride)
#define A_SC_OFF   9248               // 512*8 = 4096
#define A_PP_OFF   13344              // 256*10 = 2560
#define A_RED_OFF  15904              // wred 64 + smj 8 + slj 8
#define A_SMEM_FLOATS 15984
#define A_SMEM_BYTES  (A_SMEM_FLOATS*4)
#define QPAD 132

__device__ __forceinline__ int swiz(int r, int c) {   // 16B-chunk swizzle, 512B row
    return (c & 24) | ((c & 7) ^ (r & 7));
}

__global__ __launch_bounds__(256, 3) void attn_chunk_kernel(
    const float* __restrict__ k_cache,
    const float* __restrict__ v_cache,
    const float* __restrict__ qkv)
{
    extern __shared__ float sm[];
    const int tid  = threadIdx.x;
    const int bx   = blockIdx.x;
    const int ch   = bx & 7;
    const int bh   = bx >> 3;
    const int b    = bh >> 4;
    const int h    = bh & 15;
    const int w    = tid >> 5;
    const int lane = tid & 31;
    const int s_chunk0 = ch * CH_;

    float* tile = sm + A_TILE_OFF;
    float* qs   = sm + A_QS_OFF;
    float* sc   = sm + A_SC_OFF;
    float* pp   = sm + A_PP_OFF;
    float* wred = sm + A_RED_OFF;         // [8 warps][8]
    float* smj  = sm + A_RED_OFF + 64;    // chunk max [8]
    float* slj  = sm + A_RED_OFF + 72;    // chunk sum [8]

    unsigned tile_s = (unsigned)__cvta_generic_to_shared(tile);

    // tile loader: 1024 16B chunks per tile, thread does 4
    auto load_tile = [&](int tt, int buf) {
        int s0 = s_chunk0 + tt * 32;
        #pragma unroll
        for (int i = 0; i < 4; i++) {
            int m = tid + 256 * i;
            int rr = m >> 5, cc = m & 31;
            int s = s0 + rr;
            const float* src = (s >= STARTPOS)
                ? qkv + (size_t)(b * T_ + (s - STARTPOS)) * QKV_STRIDE + C_ + h * D_ + cc * 4
                : k_cache + ((size_t)(b * H_ + h) * MAXSEQ + s) * (size_t)D_ + cc * 4;
            unsigned dst = tile_s + ((unsigned)buf * 1024u + (unsigned)(rr * 32 + swiz(rr, cc))) * 16u;
            cp16(dst, src);
        }
        CP_COMMIT();
    };

    // prologue: issue tile 0 load, then stage q (scaled, padded stride QPAD)
    load_tile(0, 0);
    const float scale = 0.08838834764831845f;
    for (int f = tid; f < T_ * D_; f += 256) {
        int j = f >> 7, d = f & 127;
        qs[j * QPAD + d] = qkv[(size_t)(b * T_ + j) * QKV_STRIDE + h * D_ + d] * scale;
    }

    // ------- score loop: 16 tiles of 32 rows, q amortized over 2 rows -------
    const int e  = w;                     // warp owns d-chunks e*4..e*4+3
    const int rr = lane & 15;
    const int jh = lane >> 4;             // j-half
    const int rowA = rr, rowB = rr + 16;
    unsigned koffA[4], koffB[4];
    #pragma unroll
    for (int i = 0; i < 4; i++) {
        int c = e * 4 + i;
        koffA[i] = (unsigned)(rowA * 32 + swiz(rowA, c)) * 16u;
        koffB[i] = (unsigned)(rowB * 32 + swiz(rowB, c)) * 16u;
    }
    const float* qb = qs + jh * 4 * QPAD;

    for (int tt = 0; tt < 16; tt++) {
        int buf = tt & 1;
        if (tt + 1 < 16) { load_tile(tt + 1, buf ^ 1); CP_WAIT(1); }
        else             { CP_WAIT(0); }
        __syncthreads();

        const char* tb = (const char*)tile + buf * 16384;
        u64 aA[4], aB[4];
        #pragma unroll
        for (int j4 = 0; j4 < 4; j4++) { aA[j4] = 0ull; aB[j4] = 0ull; }
        #pragma unroll
        for (int i = 0; i < 4; i++) {
            int c = e * 4 + i;
            ulonglong2 kA = *(const ulonglong2*)(tb + koffA[i]);
            ulonglong2 kB = *(const ulonglong2*)(tb + koffB[i]);
            const float* qc = qb + c * 4;
            #pragma unroll
            for (int j4 = 0; j4 < 4; j4++) {
                ulonglong2 q2 = *(const ulonglong2*)(qc + j4 * QPAD);
                fma2(aA[j4], kA.x, q2.x); fma2(aA[j4], kA.y, q2.y);
                fma2(aB[j4], kB.x, q2.x); fma2(aB[j4], kB.y, q2.y);
            }
        }
        {
            float* ppr = pp + (e * 32 + rowA) * 10 + jh * 4;
            *(float2*)ppr       = make_float2(hsum2(aA[0]), hsum2(aA[1]));
            *(float2*)(ppr + 2) = make_float2(hsum2(aA[2]), hsum2(aA[3]));
            ppr = pp + (e * 32 + rowB) * 10 + jh * 4;
            *(float2*)ppr       = make_float2(hsum2(aB[0]), hsum2(aB[1]));
            *(float2*)(ppr + 2) = make_float2(hsum2(aB[2]), hsum2(aB[3]));
        }
        __syncthreads();

        // combine eighths: thread -> (r = tid>>3, j = tid&7)
        {
            int r = tid >> 3, j = tid & 7;
            float v = 0.f;
            #pragma unroll
            for (int ee = 0; ee < 8; ee++) v += pp[(ee * 32 + r) * 10 + j];
            sc[(tt * 32 + r) * 8 + j] = v;
        }
    }
    __syncthreads();

    // ------- chunk softmax stats ---------------------------------
    {
        float mx[8];
        #pragma unroll
        for (int j = 0; j < 8; j++) mx[j] = -3.4e38f;
        for (int s = tid; s < CH_; s += 256) {
            float4 a = *(const float4*)(sc + s * 8);
            float4 c = *(const float4*)(sc + s * 8 + 4);
            mx[0] = fmaxf(mx[0], a.x); mx[1] = fmaxf(mx[1], a.y);
            mx[2] = fmaxf(mx[2], a.z); mx[3] = fmaxf(mx[3], a.w);
            mx[4] = fmaxf(mx[4], c.x); mx[5] = fmaxf(mx[5], c.y);
            mx[6] = fmaxf(mx[6], c.z); mx[7] = fmaxf(mx[7], c.w);
        }
        #pragma unroll
        for (int o = 16; o; o >>= 1)
            #pragma unroll
            for (int j = 0; j < 8; j++) mx[j] = fmaxf(mx[j], __shfl_xor_sync(~0u, mx[j], o));
        if (lane == 0)
            #pragma unroll
            for (int j = 0; j < 8; j++) wred[w * 8 + j] = mx[j];
    }
    __syncthreads();
    if (tid < 8) {
        float m = wred[tid];
        for (int ww = 1; ww < 8; ww++) m = fmaxf(m, wred[ww * 8 + tid]);
        smj[tid] = m;
    }
    __syncthreads();
    {
        float m[8], sum[8];
        #pragma unroll
        for (int j = 0; j < 8; j++) { m[j] = smj[j]; sum[j] = 0.f; }
        for (int s = tid; s < CH_; s += 256) {
            float4 a = *(const float4*)(sc + s * 8);
            float4 c = *(const float4*)(sc + s * 8 + 4);
            a.x = __expf(a.x - m[0]); a.y = __expf(a.y - m[1]);
            a.z = __expf(a.z - m[2]); a.w = __expf(a.w - m[3]);
            c.x = __expf(c.x - m[4]); c.y = __expf(c.y - m[5]);
            c.z = __expf(c.z - m[6]); c.w = __expf(c.w - m[7]);
            *(float4*)(sc + s * 8)     = a;
            *(float4*)(sc + s * 8 + 4) = c;
            sum[0] += a.x; sum[1] += a.y; sum[2] += a.z; sum[3] += a.w;
            sum[4] += c.x; sum[5] += c.y; sum[6] += c.z; sum[7] += c.w;
        }
        #pragma unroll
        for (int o = 16; o; o >>= 1)
            #pragma unroll
            for (int j = 0; j < 8; j++) sum[j] += __shfl_xor_sync(~0u, sum[j], o);
        if (lane == 0)
            #pragma unroll
            for (int j = 0; j < 8; j++) wred[w * 8 + j] = sum[j];
    }
    __syncthreads();
    if (tid < 8) {
        float s = 0.f;
        for (int ww = 0; ww < 8; ww++) s += wred[ww * 8 + tid];
        slj[tid] = s;
    }

    // ------- PV: warp w covers 64 rows, lanes across d -----------
    u64 acc[8][2];
    #pragma unroll
    for (int j = 0; j < 8; j++) { acc[j][0] = 0ull; acc[j][1] = 0ull; }
    const int db = lane * 4;
    const int lbeg = w * 64;
    for (int sl = lbeg; sl < lbeg + 64; sl += 4) {
        #pragma unroll
        for (int u = 0; u < 4; u++) {
            int local = sl + u;
            int ss = s_chunk0 + local;
            const float* vrow = (ss >= STARTPOS)
                ? qkv + (size_t)(b * T_ + (ss - STARTPOS)) * QKV_STRIDE + 2 * C_ + h * D_
                : v_cache + ((size_t)(b * H_ + h) * MAXSEQ + ss) * (size_t)D_;
            ulonglong2 vv = *(const ulonglong2*)(vrow + db);
            float4 p0 = *(const float4*)(sc + local * 8);
            float4 p1 = *(const float4*)(sc + local * 8 + 4);
            float pj[8] = {p0.x, p0.y, p0.z, p0.w, p1.x, p1.y, p1.z, p1.w};
            #pragma unroll
            for (int j = 0; j < 8; j++) {
                u64 pd = dupf(pj[j]);
                fma2(acc[j][0], vv.x, pd);
                fma2(acc[j][1], vv.y, pd);
            }
        }
    }
    __syncthreads();
    float* ypart = tile;   // reuse: [8 warps][1024] = 8192 floats
    #pragma unroll
    for (int j = 0; j < 8; j++) {
        ulonglong2 st; st.x = acc[j][0]; st.y = acc[j][1];
        *(ulonglong2*)&ypart[w * 1024 + j * 128 + db] = st;
    }
    __syncthreads();
    for (int f = tid; f < 1024; f += 256) {
        float sum = 0.f;
        #pragma unroll
        for (int ww = 0; ww < 8; ww++) sum += ypart[ww * 1024 + f];
        g_py[(size_t)bx * 1024 + f] = sum;
    }
    if (tid < 8) {
        g_pm[bx * 8 + tid] = smj[tid];
        g_pl[bx * 8 + tid] = slj[tid];
    }
}

// ---------------------------------------------------------------------------
// Combine chunk partials per (b,h): log-sum-exp merge, write attT.
// ---------------------------------------------------------------------------
__global__ __launch_bounds__(256) void attn_reduce_kernel(float* __restrict__ attT)
{
    __shared__ float wgt[NCH][8];
    __shared__ float Lj[8];
    const int bh  = blockIdx.x;
    const int b   = bh >> 4;
    const int h   = bh & 15;
    const int tid = threadIdx.x;

    if (tid < 8) {
        int j = tid;
        float M = -3.4e38f;
        #pragma unroll
        for (int c = 0; c < NCH; c++)
            M = fmaxf(M, g_pm[(bh * NCH + c) * 8 + j]);
        float L = 0.f;
        #pragma unroll
        for (int c = 0; c < NCH; c++) {
            float wq = __expf(g_pm[(bh * NCH + c) * 8 + j] - M);
            wgt[c][j] = wq;
            L += g_pl[(bh * NCH + c) * 8 + j] * wq;
        }
        Lj[j] = L;
    }
    __syncthreads();

    for (int f = tid; f < 1024; f += 256) {
        int j = f >> 7, d = f & 127;
        float sum = 0.f;
        #pragma unroll
        for (int c = 0; c < NCH; c++)
            sum += g_py[(size_t)(bh * NCH + c) * 1024 + f] * wgt[c][j];
        attT[(size_t)(h * D_ + d) * M_ + b * T_ + j] = sum / Lj[j];
    }
}

// ---------------------------------------------------------------------------
extern "C" void kernel_launch(void* const* d_in, const int* in_sizes, int n_in,
                              void* d_out, int out_size)
{
    const float* x  = (const float*)d_in[0];
    const float* kc = (const float*)d_in[1];
    const float* vc = (const float*)d_in[2];
    const float* wa = (const float*)d_in[3];
    const float* ba = (const float*)d_in[4];
    const float* wp = (const float*)d_in[5];
    const float* bp = (const float*)d_in[6];
    float* out = (float*)d_out;

    float *xT, *qkv, *qkvp, *attT, *outp;
    cudaGetSymbolAddress((void**)&xT,   g_xT);
    cudaGetSymbolAddress((void**)&qkv,  g_qkv);
    cudaGetSymbolAddress((void**)&qkvp, g_qkvp);
    cudaGetSymbolAddress((void**)&attT, g_attT);
    cudaGetSymbolAddress((void**)&outp, g_outp);

    cudaFuncSetAttribute(attn_chunk_kernel,
                         cudaFuncAttributeMaxDynamicSharedMemorySize, A_SMEM_BYTES);

    // 1) transpose x -> xT
    transpose_kernel<<<(M_*C_)/256, 256>>>(x, xT);
    // 2) QKV GEMM, split-K 6 (48x6 = 288 blocks)
    gemm_splitk_kernel<<<dim3(3*C_/128, QKV_KS), 256>>>(xT, wa, ba, qkv, qkvp, 3*C_, QKV_KS);
    // 3) reduce partials into qkv
    addparts_kernel<<<(M_*3*C_/4 + 255)/256, 256>>>(qkv, qkvp, QKV_KS-1, M_*3*C_/4);
    // 4) attention chunks (2048 blocks) + merge
    attn_chunk_kernel<<<B_*H_*NCH, 256, A_SMEM_BYTES>>>(kc, vc, qkv);
    attn_reduce_kernel<<<B_*H_, 256>>>(attT);
    // 5) proj GEMM, split-K 18 (16x18 = 288 blocks)
    gemm_splitk_kernel<<<dim3(C_/128, PROJ_KS), 256>>>(attT, wp, bp, out, outp, C_, PROJ_KS);
    // 6) reduce partials into out
    addparts_kernel<<<(M_*C_/4 + 255)/256, 256>>>(out, outp, PROJ_KS-1, M_*C_/4);
}

// round 16
// speedup vs baseline: 1.0395x; 1.0118x over previous
#include <cuda_runtime.h>

// Fixed problem shapes
#define B_ 16
#define T_ 8
#define C_ 2048
#define H_ 16
#define D_ 128
#define MAXSEQ 4096
#define STARTPOS 4088
#define S_ 4096
#define QKV_STRIDE (3*C_)
#define M_ (B_*T_)          // 128
#define CH_ 512             // attention s-chunk
#define NCH 8               // S_/CH_
#define QKV_KS 6
#define PROJ_KS 18

// Scratch (static device globals: allocation-free)
__device__ float g_xT  [C_*M_];                     // x transposed [2048][128]
__device__ float g_qkv [M_*3*C_];                   // [128][6144]
__device__ float g_qkvp[(QKV_KS-1)*M_*3*C_];        // split-K partials
__device__ float g_attT[C_*M_];                     // attention out transposed
__device__ float g_outp[(PROJ_KS-1)*M_*C_];         // proj split-K partials
__device__ float g_py  [(size_t)B_*H_*NCH*T_*D_];   // PV partials
__device__ float g_pm  [B_*H_*NCH*T_];              // chunk maxes
__device__ float g_pl  [B_*H_*NCH*T_];              // chunk sums

typedef unsigned long long u64;

__device__ __forceinline__ u64 dupf(float x) {
    u64 r; unsigned xi = __float_as_uint(x);
    asm("mov.b64 %0, {%1, %1};" : "=l"(r) : "r"(xi));
    return r;
}
__device__ __forceinline__ void fma2(u64& d, u64 a, u64 b) {
    asm("fma.rn.f32x2 %0, %1, %2, %0;" : "+l"(d) : "l"(a), "l"(b));
}
__device__ __forceinline__ float2 unpk(u64 v) {
    unsigned lo, hi;
    asm("mov.b64 {%0, %1}, %2;" : "=r"(lo), "=r"(hi) : "l"(v));
    return make_float2(__uint_as_float(lo), __uint_as_float(hi));
}
__device__ __forceinline__ float hsum2(u64 v) { float2 f = unpk(v); return f.x + f.y; }

__device__ __forceinline__ void cp16(unsigned dst, const void* src) {
    asm volatile("cp.async.cg.shared.global [%0], [%1], 16;\n" :: "r"(dst), "l"(src));
}
#define CP_COMMIT()  asm volatile("cp.async.commit_group;\n" ::: "memory")
#define CP_WAIT(n)   asm volatile("cp.async.wait_group %0;\n" :: "n"(n) : "memory")

// ---------------------------------------------------------------------------
// transpose x[128][2048] -> xT[2048][128]
// ---------------------------------------------------------------------------
__global__ __launch_bounds__(256) void transpose_kernel(const float* __restrict__ x,
                                                        float* __restrict__ xT) {
    int idx = blockIdx.x * 256 + threadIdx.x;
    int r = idx >> 11;
    int c = idx & 2047;
    xT[c * M_ + r] = x[idx];
}

// ---------------------------------------------------------------------------
// GEMM: C[128][N] = AT^T[128][2048] @ B[2048][N] + bias, split-K (KS slices).
// 6-stage ring, 4 tiles in flight, ONE barrier per 2 k-blocks.
// ---------------------------------------------------------------------------
__global__ __launch_bounds__(256) void gemm_splitk_kernel(
    const float* __restrict__ AT, const float* __restrict__ Bw,
    const float* __restrict__ bias, float* __restrict__ Cc,
    float* __restrict__ Pp, int N, int KS)
{
    __shared__ float As[6][8][128];
    __shared__ float Bs[6][8][128];

    const int tid = threadIdx.x;
    const int tx = tid & 15;
    const int ty = tid >> 4;
    const int n0 = blockIdx.x * 128;
    const int slice = blockIdx.y;

    const int KBTOT = 256;
    const int kb0 = (slice * KBTOT) / KS;
    const int kb1 = ((slice + 1) * KBTOT) / KS;

    const int lr = tid >> 5;
    const int lc = tid & 31;
    unsigned sA = (unsigned)__cvta_generic_to_shared(&As[0][0][0]);
    unsigned sB = (unsigned)__cvta_generic_to_shared(&Bs[0][0][0]);

    u64 acc[4][8];
    #pragma unroll
    for (int p = 0; p < 4; p++)
        #pragma unroll
        for (int n = 0; n < 8; n++) acc[p][n] = 0ull;

    auto issue = [&](int kb, int buf) {
        int k = kb * 8 + lr;
        cp16(sA + (unsigned)(buf * 1024 + lr * 128 + lc * 4) * 4u, AT + (size_t)k * M_ + lc * 4);
        cp16(sB + (unsigned)(buf * 1024 + lr * 128 + lc * 4) * 4u, Bw + (size_t)k * N + n0 + lc * 4);
        CP_COMMIT();
    };
    auto waitN = [&](int n) {
        switch (n) {
            case 0: CP_WAIT(0); break;
            case 1: CP_WAIT(1); break;
            case 2: CP_WAIT(2); break;
            case 3: CP_WAIT(3); break;
            default: CP_WAIT(4); break;
        }
    };
    auto compute = [&](int buf) {
        #pragma unroll
        for (int kk = 0; kk < 8; kk++) {
            ulonglong2 a0 = *(const ulonglong2*)&As[buf][kk][ty * 4];
            ulonglong2 a1 = *(const ulonglong2*)&As[buf][kk][64 + ty * 4];
            float4 b0 = *(const float4*)&Bs[buf][kk][tx * 4];
            float4 b1 = *(const float4*)&Bs[buf][kk][64 + tx * 4];
            u64 bd[8];
            bd[0] = dupf(b0.x); bd[1] = dupf(b0.y); bd[2] = dupf(b0.z); bd[3] = dupf(b0.w);
            bd[4] = dupf(b1.x); bd[5] = dupf(b1.y); bd[6] = dupf(b1.z); bd[7] = dupf(b1.w);
            #pragma unroll
            for (int n = 0; n < 8; n++) {
                fma2(acc[0][n], a0.x, bd[n]);
                fma2(acc[1][n], a0.y, bd[n]);
                fma2(acc[2][n], a1.x, bd[n]);
                fma2(acc[3][n], a1.y, bd[n]);
            }
        }
    };

    const int cnt = kb1 - kb0;
    const int ahead = (cnt < 4) ? cnt : 4;
    for (int i = 0; i < ahead; i++) issue(kb0 + i, i % 6);
    int next = kb0 + ahead;
    int kb = kb0;

    if (cnt & 1) {                    // peel one single-tile iteration
        waitN(next - kb - 1);
        __syncthreads();
        if (next < kb1) { issue(next, (next - kb0) % 6); next++; }
        compute((kb - kb0) % 6);
        kb++;
    }
    for (; kb < kb1; kb += 2) {       // pair iterations: 1 barrier / 2 tiles
        waitN(next - kb - 2);
        __syncthreads();
        if (next < kb1) { issue(next, (next - kb0) % 6); next++; }
        if (next < kb1) { issue(next, (next - kb0) % 6); next++; }
        compute((kb - kb0) % 6);
        compute((kb + 1 - kb0) % 6);
    }

    float* dst = (slice == 0) ? Cc : Pp + (size_t)(slice - 1) * M_ * N;
    float4 bi0 = make_float4(0.f, 0.f, 0.f, 0.f), bi1 = bi0;
    if (slice == 0) {
        bi0 = *(const float4*)(bias + n0 + tx * 4);
        bi1 = *(const float4*)(bias + n0 + 64 + tx * 4);
    }
    #pragma unroll
    for (int p = 0; p < 4; p++) {
        int mr = (p < 2) ? (ty * 4 + 2 * p) : (64 + ty * 4 + 2 * (p - 2));
        float2 u0 = unpk(acc[p][0]), u1 = unpk(acc[p][1]), u2 = unpk(acc[p][2]), u3 = unpk(acc[p][3]);
        float2 u4 = unpk(acc[p][4]), u5 = unpk(acc[p][5]), u6 = unpk(acc[p][6]), u7 = unpk(acc[p][7]);
        float4 lo0 = make_float4(u0.x + bi0.x, u1.x + bi0.y, u2.x + bi0.z, u3.x + bi0.w);
        float4 hi0 = make_float4(u0.y + bi0.x, u1.y + bi0.y, u2.y + bi0.z, u3.y + bi0.w);
        float4 lo1 = make_float4(u4.x + bi1.x, u5.x + bi1.y, u6.x + bi1.z, u7.x + bi1.w);
        float4 hi1 = make_float4(u4.y + bi1.x, u5.y + bi1.y, u6.y + bi1.z, u7.y + bi1.w);
        *(float4*)(dst + (size_t)mr * N + n0 + tx * 4)            = lo0;
        *(float4*)(dst + (size_t)(mr + 1) * N + n0 + tx * 4)      = hi0;
        *(float4*)(dst + (size_t)mr * N + n0 + 64 + tx * 4)       = lo1;
        *(float4*)(dst + (size_t)(mr + 1) * N + n0 + 64 + tx * 4) = hi1;
    }
}

// dst[i] += sum_p parts[p][i]
__global__ __launch_bounds__(256) void addparts_kernel(float* __restrict__ dst,
                                                       const float* __restrict__ parts,
                                                       int nparts, int n4) {
    int i = blockIdx.x * 256 + threadIdx.x;
    if (i >= n4) return;
    float4 v = ((float4*)dst)[i];
    for (int p = 0; p < nparts; p++) {
        float4 a = ((const float4*)parts)[(size_t)p * n4 + i];
        v.x += a.x; v.y += a.y; v.z += a.z; v.w += a.w;
    }
    ((float4*)dst)[i] = v;
}

// ---------------------------------------------------------------------------
// Attention chunk kernel (R11/R13 proven version, unchanged):
// block per (b,h,chunk), 256 threads, 2048 blocks, 32-row K tiles x2 buffers.
// ---------------------------------------------------------------------------
// smem float offsets
#define A_TILE_OFF 0                  // 2 x 32x128 = 8192
#define A_QS_OFF   8192               // 8 x 132 = 1056 (padded stride)
#define A_SC_OFF   9248               // 512*8 = 4096
#define A_PP_OFF   13344              // 256*10 = 2560
#define A_RED_OFF  15904              // wred 64 + smj 8 + slj 8
#define A_SMEM_FLOATS 15984
#define A_SMEM_BYTES  (A_SMEM_FLOATS*4)
#define QPAD 132

__device__ __forceinline__ int swiz(int r, int c) {   // 16B-chunk swizzle, 512B row
    return (c & 24) | ((c & 7) ^ (r & 7));
}

__global__ __launch_bounds__(256, 3) void attn_chunk_kernel(
    const float* __restrict__ k_cache,
    const float* __restrict__ v_cache,
    const float* __restrict__ qkv)
{
    extern __shared__ float sm[];
    const int tid  = threadIdx.x;
    const int bx   = blockIdx.x;
    const int ch   = bx & 7;
    const int bh   = bx >> 3;
    const int b    = bh >> 4;
    const int h    = bh & 15;
    const int w    = tid >> 5;
    const int lane = tid & 31;
    const int s_chunk0 = ch * CH_;

    float* tile = sm + A_TILE_OFF;
    float* qs   = sm + A_QS_OFF;
    float* sc   = sm + A_SC_OFF;
    float* pp   = sm + A_PP_OFF;
    float* wred = sm + A_RED_OFF;         // [8 warps][8]
    float* smj  = sm + A_RED_OFF + 64;    // chunk max [8]
    float* slj  = sm + A_RED_OFF + 72;    // chunk sum [8]

    unsigned tile_s = (unsigned)__cvta_generic_to_shared(tile);

    // tile loader: 1024 16B chunks per tile, thread does 4
    auto load_tile = [&](int tt, int buf) {
        int s0 = s_chunk0 + tt * 32;
        #pragma unroll
        for (int i = 0; i < 4; i++) {
            int m = tid + 256 * i;
            int rr = m >> 5, cc = m & 31;
            int s = s0 + rr;
            const float* src = (s >= STARTPOS)
                ? qkv + (size_t)(b * T_ + (s - STARTPOS)) * QKV_STRIDE + C_ + h * D_ + cc * 4
                : k_cache + ((size_t)(b * H_ + h) * MAXSEQ + s) * (size_t)D_ + cc * 4;
            unsigned dst = tile_s + ((unsigned)buf * 1024u + (unsigned)(rr * 32 + swiz(rr, cc))) * 16u;
            cp16(dst, src);
        }
        CP_COMMIT();
    };

    // prologue: issue tile 0 load, then stage q (scaled, padded stride QPAD)
    load_tile(0, 0);
    const float scale = 0.08838834764831845f;
    for (int f = tid; f < T_ * D_; f += 256) {
        int j = f >> 7, d = f & 127;
        qs[j * QPAD + d] = qkv[(size_t)(b * T_ + j) * QKV_STRIDE + h * D_ + d] * scale;
    }

    // ------- score loop: 16 tiles of 32 rows, q amortized over 2 rows -------
    const int e  = w;                     // warp owns d-chunks e*4..e*4+3
    const int rr = lane & 15;
    const int jh = lane >> 4;             // j-half
    const int rowA = rr, rowB = rr + 16;
    unsigned koffA[4], koffB[4];
    #pragma unroll
    for (int i = 0; i < 4; i++) {
        int c = e * 4 + i;
        koffA[i] = (unsigned)(rowA * 32 + swiz(rowA, c)) * 16u;
        koffB[i] = (unsigned)(rowB * 32 + swiz(rowB, c)) * 16u;
    }
    const float* qb = qs + jh * 4 * QPAD;

    for (int tt = 0; tt < 16; tt++) {
        int buf = tt & 1;
        if (tt + 1 < 16) { load_tile(tt + 1, buf ^ 1); CP_WAIT(1); }
        else             { CP_WAIT(0); }
        __syncthreads();

        const char* tb = (const char*)tile + buf * 16384;
        u64 aA[4], aB[4];
        #pragma unroll
        for (int j4 = 0; j4 < 4; j4++) { aA[j4] = 0ull; aB[j4] = 0ull; }
        #pragma unroll
        for (int i = 0; i < 4; i++) {
            int c = e * 4 + i;
            ulonglong2 kA = *(const ulonglong2*)(tb + koffA[i]);
            ulonglong2 kB = *(const ulonglong2*)(tb + koffB[i]);
            const float* qc = qb + c * 4;
            #pragma unroll
            for (int j4 = 0; j4 < 4; j4++) {
                ulonglong2 q2 = *(const ulonglong2*)(qc + j4 * QPAD);
                fma2(aA[j4], kA.x, q2.x); fma2(aA[j4], kA.y, q2.y);
                fma2(aB[j4], kB.x, q2.x); fma2(aB[j4], kB.y, q2.y);
            }
        }
        {
            float* ppr = pp + (e * 32 + rowA) * 10 + jh * 4;
            *(float2*)ppr       = make_float2(hsum2(aA[0]), hsum2(aA[1]));
            *(float2*)(ppr + 2) = make_float2(hsum2(aA[2]), hsum2(aA[3]));
            ppr = pp + (e * 32 + rowB) * 10 + jh * 4;
            *(float2*)ppr       = make_float2(hsum2(aB[0]), hsum2(aB[1]));
            *(float2*)(ppr + 2) = make_float2(hsum2(aB[2]), hsum2(aB[3]));
        }
        __syncthreads();

        // combine eighths: thread -> (r = tid>>3, j = tid&7)
        {
            int r = tid >> 3, j = tid & 7;
            float v = 0.f;
            #pragma unroll
            for (int ee = 0; ee < 8; ee++) v += pp[(ee * 32 + r) * 10 + j];
            sc[(tt * 32 + r) * 8 + j] = v;
        }
    }
    __syncthreads();

    // ------- chunk softmax stats ---------------------------------
    {
        float mx[8];
        #pragma unroll
        for (int j = 0; j < 8; j++) mx[j] = -3.4e38f;
        for (int s = tid; s < CH_; s += 256) {
            float4 a = *(const float4*)(sc + s * 8);
            float4 c = *(const float4*)(sc + s * 8 + 4);
            mx[0] = fmaxf(mx[0], a.x); mx[1] = fmaxf(mx[1], a.y);
            mx[2] = fmaxf(mx[2], a.z); mx[3] = fmaxf(mx[3], a.w);
            mx[4] = fmaxf(mx[4], c.x); mx[5] = fmaxf(mx[5], c.y);
            mx[6] = fmaxf(mx[6], c.z); mx[7] = fmaxf(mx[7], c.w);
        }
        #pragma unroll
        for (int o = 16; o; o >>= 1)
            #pragma unroll
            for (int j = 0; j < 8; j++) mx[j] = fmaxf(mx[j], __shfl_xor_sync(~0u, mx[j], o));
        if (lane == 0)
            #pragma unroll
            for (int j = 0; j < 8; j++) wred[w * 8 + j] = mx[j];
    }
    __syncthreads();
    if (tid < 8) {
        float m = wred[tid];
        for (int ww = 1; ww < 8; ww++) m = fmaxf(m, wred[ww * 8 + tid]);
        smj[tid] = m;
    }
    __syncthreads();
    {
        float m[8], sum[8];
        #pragma unroll
        for (int j = 0; j < 8; j++) { m[j] = smj[j]; sum[j] = 0.f; }
        for (int s = tid; s < CH_; s += 256) {
            float4 a = *(const float4*)(sc + s * 8);
            float4 c = *(const float4*)(sc + s * 8 + 4);
            a.x = __expf(a.x - m[0]); a.y = __expf(a.y - m[1]);
            a.z = __expf(a.z - m[2]); a.w = __expf(a.w - m[3]);
            c.x = __expf(c.x - m[4]); c.y = __expf(c.y - m[5]);
            c.z = __expf(c.z - m[6]); c.w = __expf(c.w - m[7]);
            *(float4*)(sc + s * 8)     = a;
            *(float4*)(sc + s * 8 + 4) = c;
            sum[0] += a.x; sum[1] += a.y; sum[2] += a.z; sum[3] += a.w;
            sum[4] += c.x; sum[5] += c.y; sum[6] += c.z; sum[7] += c.w;
        }
        #pragma unroll
        for (int o = 16; o; o >>= 1)
            #pragma unroll
            for (int j = 0; j < 8; j++) sum[j] += __shfl_xor_sync(~0u, sum[j], o);
        if (lane == 0)
            #pragma unroll
            for (int j = 0; j < 8; j++) wred[w * 8 + j] = sum[j];
    }
    __syncthreads();
    if (tid < 8) {
        float s = 0.f;
        for (int ww = 0; ww < 8; ww++) s += wred[ww * 8 + tid];
        slj[tid] = s;
    }

    // ------- PV: warp w covers 64 rows, lanes across d -----------
    u64 acc[8][2];
    #pragma unroll
    for (int j = 0; j < 8; j++) { acc[j][0] = 0ull; acc[j][1] = 0ull; }
    const int db = lane * 4;
    const int lbeg = w * 64;
    for (int sl = lbeg; sl < lbeg + 64; sl += 4) {
        #pragma unroll
        for (int u = 0; u < 4; u++) {
            int local = sl + u;
            int ss = s_chunk0 + local;
            const float* vrow = (ss >= STARTPOS)
                ? qkv + (size_t)(b * T_ + (ss - STARTPOS)) * QKV_STRIDE + 2 * C_ + h * D_
                : v_cache + ((size_t)(b * H_ + h) * MAXSEQ + ss) * (size_t)D_;
            ulonglong2 vv = *(const ulonglong2*)(vrow + db);
            float4 p0 = *(const float4*)(sc + local * 8);
            float4 p1 = *(const float4*)(sc + local * 8 + 4);
            float pj[8] = {p0.x, p0.y, p0.z, p0.w, p1.x, p1.y, p1.z, p1.w};
            #pragma unroll
            for (int j = 0; j < 8; j++) {
                u64 pd = dupf(pj[j]);
                fma2(acc[j][0], vv.x, pd);
                fma2(acc[j][1], vv.y, pd);
            }
        }
    }
    __syncthreads();
    float* ypart = tile;   // reuse: [8 warps][1024] = 8192 floats
    #pragma unroll
    for (int j = 0; j < 8; j++) {
        ulonglong2 st; st.x = acc[j][0]; st.y = acc[j][1];
        *(ulonglong2*)&ypart[w * 1024 + j * 128 + db] = st;
    }
    __syncthreads();
    for (int f = tid; f < 1024; f += 256) {
        float sum = 0.f;
        #pragma unroll
        for (int ww = 0; ww < 8; ww++) sum += ypart[ww * 1024 + f];
        g_py[(size_t)bx * 1024 + f] = sum;
    }
    if (tid < 8) {
        g_pm[bx * 8 + tid] = smj[tid];
        g_pl[bx * 8 + tid] = slj[tid];
    }
}

// ---------------------------------------------------------------------------
// Combine chunk partials per (b,h): log-sum-exp merge, write attT.
// ---------------------------------------------------------------------------
__global__ __launch_bounds__(256) void attn_reduce_kernel(float* __restrict__ attT)
{
    __shared__ float wgt[NCH][8];
    __shared__ float Lj[8];
    const int bh  = blockIdx.x;
    const int b   = bh >> 4;
    const int h   = bh & 15;
    const int tid = threadIdx.x;

    if (tid < 8) {
        int j = tid;
        float M = -3.4e38f;
        #pragma unroll
        for (int c = 0; c < NCH; c++)
            M = fmaxf(M, g_pm[(bh * NCH + c) * 8 + j]);
        float L = 0.f;
        #pragma unroll
        for (int c = 0; c < NCH; c++) {
            float wq = __expf(g_pm[(bh * NCH + c) * 8 + j] - M);
            wgt[c][j] = wq;
            L += g_pl[(bh * NCH + c) * 8 + j] * wq;
        }
        Lj[j] = L;
    }
    __syncthreads();

    for (int f = tid; f < 1024; f += 256) {
        int j = f >> 7, d = f & 127;
        float sum = 0.f;
        #pragma unroll
        for (int c = 0; c < NCH; c++)
            sum += g_py[(size_t)(bh * NCH + c) * 1024 + f] * wgt[c][j];
        attT[(size_t)(h * D_ + d) * M_ + b * T_ + j] = sum / Lj[j];
    }
}

// ---------------------------------------------------------------------------
extern "C" void kernel_launch(void* const* d_in, const int* in_sizes, int n_in,
                              void* d_out, int out_size)
{
    const float* x  = (const float*)d_in[0];
    const float* kc = (const float*)d_in[1];
    const float* vc = (const float*)d_in[2];
    const float* wa = (const float*)d_in[3];
    const float* ba = (const float*)d_in[4];
    const float* wp = (const float*)d_in[5];
    const float* bp = (const float*)d_in[6];
    float* out = (float*)d_out;

    float *xT, *qkv, *qkvp, *attT, *outp;
    cudaGetSymbolAddress((void**)&xT,   g_xT);
    cudaGetSymbolAddress((void**)&qkv,  g_qkv);
    cudaGetSymbolAddress((void**)&qkvp, g_qkvp);
    cudaGetSymbolAddress((void**)&attT, g_attT);
    cudaGetSymbolAddress((void**)&outp, g_outp);

    cudaFuncSetAttribute(attn_chunk_kernel,
                         cudaFuncAttributeMaxDynamicSharedMemorySize, A_SMEM_BYTES);

    // 1) transpose x -> xT
    transpose_kernel<<<(M_*C_)/256, 256>>>(x, xT);
    // 2) QKV GEMM, split-K 6 (48x6 = 288 blocks)
    gemm_splitk_kernel<<<dim3(3*C_/128, QKV_KS), 256>>>(xT, wa, ba, qkv, qkvp, 3*C_, QKV_KS);
    // 3) reduce partials into qkv
    addparts_kernel<<<(M_*3*C_/4 + 255)/256, 256>>>(qkv, qkvp, QKV_KS-1, M_*3*C_/4);
    // 4) attention chunks (2048 blocks) + merge
    attn_chunk_kernel<<<B_*H_*NCH, 256, A_SMEM_BYTES>>>(kc, vc, qkv);
    attn_reduce_kernel<<<B_*H_, 256>>>(attT);
    // 5) proj GEMM, split-K 18 (16x18 = 288 blocks)
    gemm_splitk_kernel<<<dim3(C_/128, PROJ_KS), 256>>>(attT, wp, bp, out, outp, C_, PROJ_KS);
    // 6) reduce partials into out
    addparts_kernel<<<(M_*C_/4 + 255)/256, 256>>>(out, outp, PROJ_KS-1, M_*C_/4);
}